// round 9
// baseline (speedup 1.0000x reference)
#include <cuda_runtime.h>
#include <cstdint>

#define BB 32
#define TT 800
#define LL 60
#define HH 512
#define DD 1024
#define AA 512
#define FCN 16
#define KCV 101
#define CC 4000
#define NSPK 8
#define NSPT 16

typedef unsigned long long ull;

// ---------------- static device scratch ----------------
__device__ float g_hE[BB * TT * AA];
__device__ float g_recpre[BB * LL * 2048];
__device__ float g_WscatT[3072 * 512];   // [k/4][n][4] packed transposed
__device__ float g_WgcatT[2560 * 1024];  // [k/4][n][4] packed transposed
__device__ float g_spart[NSPK * BB * 3072];
__device__ float g_gpart[NSPK * BB * 2560];
__device__ float g_gp2[NSPT * BB * DD];
__device__ float g_e[BB * TT];
__device__ float g_alpha[BB * TT];
__device__ float g_ypre_all[LL * BB * HH];
__device__ float g_s[BB * HH];
__device__ float g_c[BB * HH];

__device__ __forceinline__ void fma2(ull& d, ull a, ull b) {
    asm("fma.rn.f32x2 %0, %1, %2, %0;" : "+l"(d) : "l"(a), "l"(b));
}
__device__ __forceinline__ ull add2(ull a, ull b) {
    ull r;
    asm("add.rn.f32x2 %0, %1, %2;" : "=l"(r) : "l"(a), "l"(b));
    return r;
}
__device__ __forceinline__ ull pack2(float x) {
    ull r;
    asm("mov.b64 %0, {%1, %1};" : "=l"(r) : "f"(x));
    return r;
}
__device__ __forceinline__ float2 unpk(ull v) {
    float2 f;
    asm("mov.b64 {%0,%1}, %2;" : "=f"(f.x), "=f"(f.y) : "l"(v));
    return f;
}
__device__ __forceinline__ float tanh_fast(float x) {
    float e2 = __expf(2.f * x);
    return 1.f - 2.f / (e2 + 1.f);
}
__device__ __forceinline__ float sig_acc(float x) {
    return tanhf(0.5f * x) * 0.5f + 0.5f;
}

// ---------------- init: zero state, build TRANSPOSED packed weights ----------------
__global__ void k_init(const float* __restrict__ W_se, const float* __restrict__ W_sy,
                       const float* __restrict__ W_ss, const float* __restrict__ W_gy,
                       const float* __restrict__ W_gs) {
    int i0 = blockIdx.x * blockDim.x + threadIdx.x;
    int st = gridDim.x * blockDim.x;
    for (int i = i0; i < BB * HH; i += st) { g_s[i] = 0.f; g_c[i] = 0.f; }
    for (int i = i0; i < BB * TT; i += st) g_alpha[i] = 0.f;
    // Wscat rows: [W_se(512); W_sy(512); W_ss(2048)], K=512
    for (int i = i0; i < 3072 * 512; i += st) {
        int r = i >> 9, k = i & 511;
        float v;
        if (r < 512)       v = W_se[i];
        else if (r < 1024) v = W_sy[(r - 512) * 512 + k];
        else               v = W_ss[(r - 1024) * 512 + k];
        g_WscatT[(((k >> 2) * 3072) + r) * 4 + (k & 3)] = v;
    }
    // Wgcat rows: [W_gy(512); W_gs(2048)], K=1024
    for (int i = i0; i < 2560 * 1024; i += st) {
        int r = i >> 10, k = i & 1023;
        float v = (r < 512) ? W_gy[i] : W_gs[(r - 512) * 1024 + k];
        g_WgcatT[(((k >> 2) * 2560) + r) * 4 + (k & 3)] = v;
    }
}

// ---------------- big GEMM (FFMA2): Out[M,N]=A[M,K]@W[N,K]^T ----------------
template <int MODE>
__global__ __launch_bounds__(256) void k_gemm_big(
    const float* __restrict__ A, const float* __restrict__ W,
    const float* __restrict__ bias, float* __restrict__ outx,
    int lda, int ldw, int K) {
    __shared__ __align__(16) float As[16][132];
    __shared__ __align__(16) float Bs[16][132];
    const float* Ap = (MODE == 2) ? g_ypre_all : A;
    int t = threadIdx.x;
    int n0 = blockIdx.x * 128, m0 = blockIdx.y * 128;
    int tr = t >> 4, tc = t & 15;
    ull acc2[4][8];
#pragma unroll
    for (int i = 0; i < 4; i++)
#pragma unroll
        for (int j = 0; j < 8; j++) acc2[i][j] = 0ull;

    for (int k0 = 0; k0 < K; k0 += 16) {
#pragma unroll
        for (int j = 0; j < 8; j++) {
            int e = t + j * 256;
            int m = e >> 4, k = e & 15;
            As[k][m] = Ap[(size_t)(m0 + m) * lda + k0 + k];
            int n = n0 + m;
            float wv = 0.f;
            if (MODE != 2 || n < CC) wv = W[(size_t)n * ldw + k0 + k];
            Bs[k][m] = wv;
        }
        __syncthreads();
#pragma unroll
        for (int k = 0; k < 16; k++) {
            ulonglong2 aA = *(const ulonglong2*)&As[k][tr * 8];
            ulonglong2 aB = *(const ulonglong2*)&As[k][tr * 8 + 4];
            ull ap[4] = {aA.x, aA.y, aB.x, aB.y};
            float4 b0 = *(const float4*)&Bs[k][tc * 8];
            float4 b1 = *(const float4*)&Bs[k][tc * 8 + 4];
            ull bp[8] = {pack2(b0.x), pack2(b0.y), pack2(b0.z), pack2(b0.w),
                         pack2(b1.x), pack2(b1.y), pack2(b1.z), pack2(b1.w)};
#pragma unroll
            for (int i = 0; i < 4; i++)
#pragma unroll
                for (int j = 0; j < 8; j++) fma2(acc2[i][j], ap[i], bp[j]);
        }
        __syncthreads();
    }
#pragma unroll
    for (int mp = 0; mp < 4; mp++) {
        float r0[8], r1[8];
#pragma unroll
        for (int j = 0; j < 8; j++) {
            float2 v = unpk(acc2[mp][j]);
            int n = n0 + tc * 8 + j;
            float bv = (MODE == 0) ? 0.f : ((MODE == 2 && n >= CC) ? 0.f : bias[n]);
            r0[j] = v.x + bv;
            r1[j] = v.y + bv;
        }
        int me = m0 + tr * 8 + 2 * mp;
        int nn = n0 + tc * 8;
#pragma unroll
        for (int rr = 0; rr < 2; rr++) {
            int m = me + rr;
            const float* src = rr ? r1 : r0;
            float* orow;
            if (MODE == 0)      orow = &g_hE[(size_t)m * 512];
            else if (MODE == 1) orow = &g_recpre[(size_t)m * 2048];
            else {
                int l = m >> 5, b = m & 31;
                orow = outx + (size_t)b * LL * CC + (size_t)l * CC;
            }
            if (MODE != 2 || nn + 7 < CC) {
                *(float4*)&orow[nn] = make_float4(src[0], src[1], src[2], src[3]);
                *(float4*)&orow[nn + 4] = make_float4(src[4], src[5], src[6], src[7]);
            } else {
#pragma unroll
                for (int j = 0; j < 8; j++)
                    if (nn + j < CC) orow[nn + j] = src[j];
            }
        }
    }
}

// ---------------- skinny GEMM: thread-per-n, k-major packed weights ----------------
// MODE 0: s @ Wscat^T (N=3072,K=512,KS=64)   grid (12,8)
// MODE 1: g @ Wgcat^T (N=2560,K=1024,KS=128) grid (10,8); A = sum of 16 gp2 partials
template <int MODE>
__global__ __launch_bounds__(256) void k_skinny() {
    constexpr int N = MODE ? 2560 : 3072;
    constexpr int K = MODE ? 1024 : 512;
    constexpr int KS = K / NSPK;
    constexpr int NBATCH = KS / 64;
    __shared__ __align__(16) float As[KS][36];
    int tid = threadIdx.x;
    int n = blockIdx.x * 256 + tid;
    int z = blockIdx.y, kb = z * KS;
    const float4* WT = (const float4*)(MODE ? g_WgcatT : g_WscatT);
    float* Out = MODE ? (g_gpart + z * BB * 2560) : (g_spart + z * BB * 3072);
    int kk0 = kb >> 2;

    // batch 0: 16 coalesced LDG.128 (should be L2 hits with hbatch marked evict-first)
    float4 w[16];
#pragma unroll
    for (int i = 0; i < 16; i++) w[i] = WT[(size_t)(kk0 + i) * N + n];

    if (MODE == 0) {
        for (int i = tid; i < 32 * KS; i += 256) {
            int m = i / KS, k = i % KS;
            As[k][m] = g_s[m * K + kb + k];
        }
    } else {
        for (int i = tid; i < 32 * KS; i += 256) {
            int m = i / KS, k = i % KS;
            float v = 0.f;
#pragma unroll
            for (int p = 0; p < NSPT; p++) v += g_gp2[p * BB * DD + m * DD + kb + k];
            As[k][m] = v;
        }
    }
    __syncthreads();

    ull acc[16];
#pragma unroll
    for (int mp = 0; mp < 16; mp++) acc[mp] = 0ull;

#pragma unroll
    for (int bt = 0; bt < NBATCH; bt++) {
        if (bt > 0) {
#pragma unroll
            for (int i = 0; i < 16; i++)
                w[i] = WT[(size_t)(kk0 + bt * 16 + i) * N + n];
        }
#pragma unroll
        for (int k4 = 0; k4 < 16; k4++) {
            float wf[4] = {w[k4].x, w[k4].y, w[k4].z, w[k4].w};
#pragma unroll
            for (int q = 0; q < 4; q++) {
                ull wp = pack2(wf[q]);
                int k = bt * 64 + k4 * 4 + q;
#pragma unroll
                for (int mp = 0; mp < 16; mp++) {
                    ull a = *(const ull*)&As[k][2 * mp];
                    fma2(acc[mp], a, wp);
                }
            }
        }
    }
#pragma unroll
    for (int mp = 0; mp < 16; mp++) {
        float2 v = unpk(acc[mp]);
        Out[(2 * mp) * N + n] = v.x;
        Out[(2 * mp + 1) * N + n] = v.y;
    }
}

// ---------------- fused attention scoring (sums sE partials itself) ----------------
__global__ __launch_bounds__(256) void k_attn(const int* __restrict__ lengths,
                                              const float* __restrict__ W_fe,
                                              const float* __restrict__ conv_w,
                                              const float* __restrict__ conv_b,
                                              const float* __restrict__ w_ee) {
    __shared__ float sE_s[AA];
    __shared__ float wee_s[AA];
    __shared__ float convw_s[FCN * KCV];
    __shared__ float convb_s[FCN];
    __shared__ float alpha_s[132];
    __shared__ __align__(16) float WfeT[FCN * 516];
    int b = blockIdx.y;
    int t0 = blockIdx.x * 32;
    int tid = threadIdx.x;
    int len = lengths[b];
    if (t0 >= len) {
        if (tid < 32) g_e[b * TT + t0 + tid] = -1e30f;
        return;
    }
    for (int a = tid; a < AA; a += 256) {
        float v = 0.f;
#pragma unroll
        for (int p = 0; p < NSPK; p++) v += g_spart[p * BB * 3072 + b * 3072 + a];
        sE_s[a] = v;
        wee_s[a] = w_ee[a];
    }
    for (int i = tid; i < FCN * KCV; i += 256) convw_s[i] = conv_w[i];
    if (tid < FCN) convb_s[tid] = conv_b[tid];
    for (int i = tid; i < AA * FCN; i += 256) {
        int a = i >> 4, f = i & 15;
        WfeT[f * 516 + a] = W_fe[i];
    }
    if (tid < 132) {
        int tg = t0 - 50 + tid;
        alpha_s[tid] = (tg >= 0 && tg < TT) ? g_alpha[b * TT + tg] : 0.f;
    }
    __syncthreads();
    int w = tid >> 5, lane = tid & 31;
    for (int tt = w; tt < 32; tt += 8) {
        int tabs = t0 + tt;
        if (tabs >= len) {
            if (lane == 0) g_e[b * TT + tabs] = -1e30f;
            continue;
        }
        int f = lane & 15, half = lane >> 4;
        float yp = 0.f;
        int ks = half * 51, ke = half ? KCV : 51;
        for (int k = ks; k < ke; k++)
            yp = fmaf(alpha_s[tt + k], convw_s[f * KCV + k], yp);
        yp += __shfl_down_sync(0xffffffffu, yp, 16);
        if (half == 0) yp += convb_s[f];
        ull yp2[16];
#pragma unroll
        for (int ff = 0; ff < 16; ff++) yp2[ff] = pack2(__shfl_sync(0xffffffffu, yp, ff));
        const float* hEr = g_hE + ((size_t)b * TT + tabs) * AA;
        ull v2[8];
#pragma unroll
        for (int c = 0; c < 4; c++) {
            ulonglong2 h2 = *(const ulonglong2*)&hEr[c * 128 + lane * 4];
            ulonglong2 s2 = *(const ulonglong2*)&sE_s[c * 128 + lane * 4];
            v2[2 * c] = add2(h2.x, s2.x);
            v2[2 * c + 1] = add2(h2.y, s2.y);
        }
#pragma unroll
        for (int ff = 0; ff < 16; ff++) {
#pragma unroll
            for (int c = 0; c < 4; c++) {
                ulonglong2 w2 = *(const ulonglong2*)&WfeT[ff * 516 + c * 128 + lane * 4];
                fma2(v2[2 * c], yp2[ff], w2.x);
                fma2(v2[2 * c + 1], yp2[ff], w2.y);
            }
        }
        float acc = 0.f;
#pragma unroll
        for (int c = 0; c < 4; c++) {
            float4 we = *(const float4*)&wee_s[c * 128 + lane * 4];
            float2 a0 = unpk(v2[2 * c]);
            float2 a1 = unpk(v2[2 * c + 1]);
            acc = fmaf(tanh_fast(a0.x), we.x, acc);
            acc = fmaf(tanh_fast(a0.y), we.y, acc);
            acc = fmaf(tanh_fast(a1.x), we.z, acc);
            acc = fmaf(tanh_fast(a1.y), we.w, acc);
        }
#pragma unroll
        for (int off = 16; off; off >>= 1) acc += __shfl_down_sync(0xffffffffu, acc, off);
        if (lane == 0) g_e[b * TT + tabs] = acc;
    }
}

// ---------------- fused softmax + g = alpha @ hbatch (evict-first hbatch stream) ----------------
__global__ __launch_bounds__(256) void k_gaccum(const float* __restrict__ hbatch,
                                                const int* __restrict__ lengths) {
    int b = blockIdx.x, ts = blockIdx.y;
    int tid = threadIdx.x;
    __shared__ float es[TT];
    __shared__ float red[256];
    float mx = -3e38f;
    for (int t2 = tid; t2 < TT; t2 += 256) {
        float v = g_e[b * TT + t2];
        es[t2] = v;
        mx = fmaxf(mx, v);
    }
    red[tid] = mx;
    __syncthreads();
    for (int o = 128; o; o >>= 1) {
        if (tid < o) red[tid] = fmaxf(red[tid], red[tid + o]);
        __syncthreads();
    }
    float M = red[0];
    __syncthreads();
    float sm = 0.f;
    for (int t2 = tid; t2 < TT; t2 += 256) {
        float p = __expf(es[t2] - M);
        es[t2] = p;
        sm += p;
    }
    red[tid] = sm;
    __syncthreads();
    for (int o = 128; o; o >>= 1) {
        if (tid < o) red[tid] += red[tid + o];
        __syncthreads();
    }
    float inv = 1.f / red[0];
    __syncthreads();
    for (int t2 = tid; t2 < TT; t2 += 256) es[t2] *= inv;
    __syncthreads();
    if (ts == 0)
        for (int t2 = tid; t2 < TT; t2 += 256) g_alpha[b * TT + t2] = es[t2];

    int len = lengths[b];
    int t1 = (len * ts) / NSPT, t2e = (len * (ts + 1)) / NSPT;
    int d = tid * 4;
    float4 acc = make_float4(0.f, 0.f, 0.f, 0.f);
    const float* hb = hbatch + (size_t)b * TT * DD + d;
    int t = t1;
    for (; t + 4 <= t2e; t += 4) {
        float a0 = es[t], a1 = es[t + 1], a2 = es[t + 2], a3 = es[t + 3];
        float4 h0 = __ldcs((const float4*)&hb[(size_t)t * DD]);
        float4 h1 = __ldcs((const float4*)&hb[(size_t)(t + 1) * DD]);
        float4 h2 = __ldcs((const float4*)&hb[(size_t)(t + 2) * DD]);
        float4 h3 = __ldcs((const float4*)&hb[(size_t)(t + 3) * DD]);
        acc.x = fmaf(a0, h0.x, fmaf(a1, h1.x, fmaf(a2, h2.x, fmaf(a3, h3.x, acc.x))));
        acc.y = fmaf(a0, h0.y, fmaf(a1, h1.y, fmaf(a2, h2.y, fmaf(a3, h3.y, acc.y))));
        acc.z = fmaf(a0, h0.z, fmaf(a1, h1.z, fmaf(a2, h2.z, fmaf(a3, h3.z, acc.z))));
        acc.w = fmaf(a0, h0.w, fmaf(a1, h1.w, fmaf(a2, h2.w, fmaf(a3, h3.w, acc.w))));
    }
    for (; t < t2e; t++) {
        float a0 = es[t];
        float4 h0 = __ldcs((const float4*)&hb[(size_t)t * DD]);
        acc.x = fmaf(a0, h0.x, acc.x);
        acc.y = fmaf(a0, h0.y, acc.y);
        acc.z = fmaf(a0, h0.z, acc.z);
        acc.w = fmaf(a0, h0.w, acc.w);
    }
    *(float4*)&g_gp2[ts * BB * DD + b * DD + d] = acc;
}

// ---------------- LSTM cell + ypre (sums partials itself, recpre evict-first) ----------------
__global__ __launch_bounds__(512) void k_cell(const float* __restrict__ b_gy, int l) {
    int b = blockIdx.x, h = threadIdx.x;
    float gy = 0.f, sy = 0.f;
#pragma unroll
    for (int p = 0; p < NSPK; p++) {
        gy += g_gpart[p * BB * 2560 + b * 2560 + h];
        sy += g_spart[p * BB * 3072 + b * 3072 + 512 + h];
    }
    float ypre = tanhf(gy + sy + b_gy[h]);
    g_ypre_all[((size_t)l * BB + b) * HH + h] = ypre;
    float r[4];
#pragma unroll
    for (int q = 0; q < 4; q++) {
        int j = q * 512 + h;
        float v = __ldcs(&g_recpre[((size_t)b * LL + l) * 2048 + j]);
#pragma unroll
        for (int p = 0; p < NSPK; p++) {
            v += g_spart[p * BB * 3072 + b * 3072 + 1024 + j];
            v += g_gpart[p * BB * 2560 + b * 2560 + 512 + j];
        }
        r[q] = v;
    }
    float c = sig_acc(r[1]) * g_c[b * HH + h] + sig_acc(r[0]) * tanhf(r[2]);
    float s = sig_acc(r[3]) * tanhf(c);
    g_c[b * HH + h] = c;
    g_s[b * HH + h] = s;
}

// ---------------- launch ----------------
extern "C" void kernel_launch(void* const* d_in, const int* in_sizes, int n_in,
                              void* d_out, int out_size) {
    const float* hbatch  = (const float*)d_in[0];
    const int*   lengths = (const int*)d_in[1];
    const float* targets = (const float*)d_in[2];
    const float* W_sy    = (const float*)d_in[3];
    const float* W_gy    = (const float*)d_in[4];
    const float* b_gy    = (const float*)d_in[5];
    const float* W_yy    = (const float*)d_in[6];
    const float* b_yy    = (const float*)d_in[7];
    const float* W_ys    = (const float*)d_in[8];
    const float* W_ss    = (const float*)d_in[9];
    const float* W_gs    = (const float*)d_in[10];
    const float* b_gs    = (const float*)d_in[11];
    const float* W_se    = (const float*)d_in[12];
    const float* W_he    = (const float*)d_in[13];
    const float* W_fe    = (const float*)d_in[14];
    const float* conv_w  = (const float*)d_in[15];
    const float* conv_b  = (const float*)d_in[16];
    const float* w_ee    = (const float*)d_in[17];
    float* out = (float*)d_out;

    k_init<<<2048, 256>>>(W_se, W_sy, W_ss, W_gy, W_gs);
    // hE = hbatch @ W_he^T : [25600,512], K=1024
    k_gemm_big<0><<<dim3(4, 200), 256>>>(hbatch, W_he, nullptr, nullptr, 1024, 1024, 1024);
    // recpre = targets @ W_ys^T + b_gs : [1920,2048], K=4000
    k_gemm_big<1><<<dim3(16, 15), 256>>>(targets, W_ys, b_gs, nullptr, 4000, 4000, 4000);

    for (int l = 0; l < LL; l++) {
        k_skinny<0><<<dim3(12, NSPK), 256>>>();
        k_attn<<<dim3(25, 32), 256>>>(lengths, W_fe, conv_w, conv_b, w_ee);
        k_gaccum<<<dim3(32, NSPT), 256>>>(hbatch, lengths);
        k_skinny<1><<<dim3(10, NSPK), 256>>>();
        k_cell<<<32, 512>>>(b_gy, l);
    }
    // y = ypre_all @ W_yy^T + b_yy : [1920,4000], K=512 -> out
    k_gemm_big<2><<<dim3(32, 15), 256>>>(nullptr, W_yy, b_yy, out, 512, 512, 512);
}

// round 11
// speedup vs baseline: 1.6301x; 1.6301x over previous
#include <cuda_runtime.h>
#include <cstdint>

#define BB 32
#define TT 800
#define LL 60
#define HH 512
#define DD 1024
#define AA 512
#define FCN 16
#define KCV 101
#define CC 4000
#define NSPK 8
#define NSPT 16

typedef unsigned long long ull;

// ---------------- static device scratch ----------------
__device__ float g_hE[BB * TT * AA];
__device__ float g_recpre[BB * LL * 2048];   // l-major: row = l*32 + b
__device__ float g_WscatT[3072 * 512];       // [k/4][n][4] packed transposed
__device__ float g_WgcatT[2560 * 1024];      // [k/4][n][4] packed transposed
__device__ float g_spart[NSPK * BB * 3072];
__device__ float g_gpart[NSPK * BB * 2560];
__device__ float g_gp2[NSPT * BB * DD];
__device__ float g_g[BB * DD];
__device__ float g_e[BB * TT];
__device__ float g_alpha[BB * TT];
__device__ float g_ypre_all[LL * BB * HH];
__device__ float g_s[BB * HH];
__device__ float g_c[BB * HH];

__device__ __forceinline__ void fma2(ull& d, ull a, ull b) {
    asm("fma.rn.f32x2 %0, %1, %2, %0;" : "+l"(d) : "l"(a), "l"(b));
}
__device__ __forceinline__ ull add2(ull a, ull b) {
    ull r;
    asm("add.rn.f32x2 %0, %1, %2;" : "=l"(r) : "l"(a), "l"(b));
    return r;
}
__device__ __forceinline__ ull pack2(float x) {
    ull r;
    asm("mov.b64 %0, {%1, %1};" : "=l"(r) : "f"(x));
    return r;
}
__device__ __forceinline__ float2 unpk(ull v) {
    float2 f;
    asm("mov.b64 {%0,%1}, %2;" : "=f"(f.x), "=f"(f.y) : "l"(v));
    return f;
}
__device__ __forceinline__ float tanh_fast(float x) {
    float e2 = __expf(2.f * x);
    return 1.f - 2.f / (e2 + 1.f);
}
__device__ __forceinline__ float sig_acc(float x) {
    return tanhf(0.5f * x) * 0.5f + 0.5f;
}

// ---------------- init: zero state, build TRANSPOSED packed weights ----------------
__global__ void k_init(const float* __restrict__ W_se, const float* __restrict__ W_sy,
                       const float* __restrict__ W_ss, const float* __restrict__ W_gy,
                       const float* __restrict__ W_gs) {
    int i0 = blockIdx.x * blockDim.x + threadIdx.x;
    int st = gridDim.x * blockDim.x;
    for (int i = i0; i < BB * HH; i += st) { g_s[i] = 0.f; g_c[i] = 0.f; }
    for (int i = i0; i < BB * TT; i += st) g_alpha[i] = 0.f;
    // Wscat rows: [W_se(512); W_sy(512); W_ss(2048)], K=512
    for (int i = i0; i < 3072 * 512; i += st) {
        int r = i >> 9, k = i & 511;
        float v;
        if (r < 512)       v = W_se[i];
        else if (r < 1024) v = W_sy[(r - 512) * 512 + k];
        else               v = W_ss[(r - 1024) * 512 + k];
        g_WscatT[(((k >> 2) * 3072) + r) * 4 + (k & 3)] = v;
    }
    // Wgcat rows: [W_gy(512); W_gs(2048)], K=1024
    for (int i = i0; i < 2560 * 1024; i += st) {
        int r = i >> 10, k = i & 1023;
        float v = (r < 512) ? W_gy[i] : W_gs[(r - 512) * 1024 + k];
        g_WgcatT[(((k >> 2) * 2560) + r) * 4 + (k & 3)] = v;
    }
}

// ---------------- big GEMM (FFMA2): Out[M,N]=A[M,K]@W[N,K]^T ----------------
// MODE 0: -> g_hE     MODE 1: -> g_recpre (l-major rows, A=targets indirect, +b_gs)
// MODE 2: g_ypre_all -> out (+b_yy)
template <int MODE>
__global__ __launch_bounds__(256) void k_gemm_big(
    const float* __restrict__ A, const float* __restrict__ W,
    const float* __restrict__ bias, float* __restrict__ outx,
    int lda, int ldw, int K, int mbase) {
    __shared__ __align__(16) float As[16][132];
    __shared__ __align__(16) float Bs[16][132];
    const float* Ap = (MODE == 2) ? g_ypre_all : A;
    int t = threadIdx.x;
    int n0 = blockIdx.x * 128, m0 = mbase + blockIdx.y * 128;
    int tr = t >> 4, tc = t & 15;
    ull acc2[4][8];
#pragma unroll
    for (int i = 0; i < 4; i++)
#pragma unroll
        for (int j = 0; j < 8; j++) acc2[i][j] = 0ull;

    for (int k0 = 0; k0 < K; k0 += 16) {
#pragma unroll
        for (int j = 0; j < 8; j++) {
            int e = t + j * 256;
            int m = e >> 4, k = e & 15;
            int mm = m0 + m;
            size_t arow;
            if (MODE == 1) arow = (size_t)((mm & 31) * LL + (mm >> 5)) * lda;  // l-major logical -> targets[b][l]
            else           arow = (size_t)mm * lda;
            As[k][m] = Ap[arow + k0 + k];
            int n = n0 + m;
            float wv = 0.f;
            if (MODE != 2 || n < CC) wv = W[(size_t)n * ldw + k0 + k];
            Bs[k][m] = wv;
        }
        __syncthreads();
#pragma unroll
        for (int k = 0; k < 16; k++) {
            ulonglong2 aA = *(const ulonglong2*)&As[k][tr * 8];
            ulonglong2 aB = *(const ulonglong2*)&As[k][tr * 8 + 4];
            ull ap[4] = {aA.x, aA.y, aB.x, aB.y};
            float4 b0 = *(const float4*)&Bs[k][tc * 8];
            float4 b1 = *(const float4*)&Bs[k][tc * 8 + 4];
            ull bp[8] = {pack2(b0.x), pack2(b0.y), pack2(b0.z), pack2(b0.w),
                         pack2(b1.x), pack2(b1.y), pack2(b1.z), pack2(b1.w)};
#pragma unroll
            for (int i = 0; i < 4; i++)
#pragma unroll
                for (int j = 0; j < 8; j++) fma2(acc2[i][j], ap[i], bp[j]);
        }
        __syncthreads();
    }
#pragma unroll
    for (int mp = 0; mp < 4; mp++) {
        float r0[8], r1[8];
#pragma unroll
        for (int j = 0; j < 8; j++) {
            float2 v = unpk(acc2[mp][j]);
            int n = n0 + tc * 8 + j;
            float bv = (MODE == 0) ? 0.f : ((MODE == 2 && n >= CC) ? 0.f : bias[n]);
            r0[j] = v.x + bv;
            r1[j] = v.y + bv;
        }
        int me = m0 + tr * 8 + 2 * mp;
        int nn = n0 + tc * 8;
#pragma unroll
        for (int rr = 0; rr < 2; rr++) {
            int m = me + rr;
            const float* src = rr ? r1 : r0;
            float* orow;
            if (MODE == 0)      orow = &g_hE[(size_t)m * 512];
            else if (MODE == 1) orow = &g_recpre[(size_t)m * 2048];
            else {
                int l = m >> 5, b = m & 31;
                orow = outx + (size_t)b * LL * CC + (size_t)l * CC;
            }
            if (MODE != 2 || nn + 7 < CC) {
                *(float4*)&orow[nn] = make_float4(src[0], src[1], src[2], src[3]);
                *(float4*)&orow[nn + 4] = make_float4(src[4], src[5], src[6], src[7]);
            } else {
#pragma unroll
                for (int j = 0; j < 8; j++)
                    if (nn + j < CC) orow[nn + j] = src[j];
            }
        }
    }
}

// ---------------- skinny GEMM: thread-per-n, k-major packed weights ----------------
// MODE 0: s @ Wscat^T (N=3072,K=512,KS=64)   grid (12,8)
// MODE 1: g @ Wgcat^T (N=2560,K=1024,KS=128) grid (10,8)
template <int MODE>
__global__ __launch_bounds__(256) void k_skinny() {
    constexpr int N = MODE ? 2560 : 3072;
    constexpr int K = MODE ? 1024 : 512;
    constexpr int KS = K / NSPK;
    constexpr int NBATCH = KS / 64;
    __shared__ __align__(16) float As[KS][36];
    int tid = threadIdx.x;
    int n = blockIdx.x * 256 + tid;
    int z = blockIdx.y, kb = z * KS;
    const float4* WT = (const float4*)(MODE ? g_WgcatT : g_WscatT);
    const float* Ain = MODE ? g_g : g_s;
    float* Out = MODE ? (g_gpart + z * BB * 2560) : (g_spart + z * BB * 3072);
    int kk0 = kb >> 2;

    float4 w[16];
#pragma unroll
    for (int i = 0; i < 16; i++) w[i] = WT[(size_t)(kk0 + i) * N + n];

    for (int i = tid; i < 32 * KS; i += 256) {
        int m = i / KS, k = i % KS;
        As[k][m] = Ain[m * K + kb + k];
    }
    __syncthreads();

    ull acc[16];
#pragma unroll
    for (int mp = 0; mp < 16; mp++) acc[mp] = 0ull;

#pragma unroll
    for (int bt = 0; bt < NBATCH; bt++) {
        if (bt > 0) {
#pragma unroll
            for (int i = 0; i < 16; i++)
                w[i] = WT[(size_t)(kk0 + bt * 16 + i) * N + n];
        }
#pragma unroll
        for (int k4 = 0; k4 < 16; k4++) {
            float wf[4] = {w[k4].x, w[k4].y, w[k4].z, w[k4].w};
#pragma unroll
            for (int q = 0; q < 4; q++) {
                ull wp = pack2(wf[q]);
                int k = bt * 64 + k4 * 4 + q;
#pragma unroll
                for (int mp = 0; mp < 16; mp++) {
                    ull a = *(const ull*)&As[k][2 * mp];
                    fma2(acc[mp], a, wp);
                }
            }
        }
    }
#pragma unroll
    for (int mp = 0; mp < 16; mp++) {
        float2 v = unpk(acc[mp]);
        Out[(2 * mp) * N + n] = v.x;
        Out[(2 * mp + 1) * N + n] = v.y;
    }
}

// ---------------- reduce t-split partials of g -> g_g ----------------
__global__ void k_gsum() {
    int b = blockIdx.x, d = threadIdx.x * 4;
    float4 acc = make_float4(0.f, 0.f, 0.f, 0.f);
#pragma unroll
    for (int p = 0; p < NSPT; p++) {
        float4 x = *(const float4*)&g_gp2[p * BB * DD + b * DD + d];
        acc.x += x.x; acc.y += x.y; acc.z += x.z; acc.w += x.w;
    }
    *(float4*)&g_g[b * DD + d] = acc;
}

// ---------------- fused attention scoring (sums sE partials itself) ----------------
__global__ __launch_bounds__(256) void k_attn(const int* __restrict__ lengths,
                                              const float* __restrict__ W_fe,
                                              const float* __restrict__ conv_w,
                                              const float* __restrict__ conv_b,
                                              const float* __restrict__ w_ee) {
    __shared__ float sE_s[AA];
    __shared__ float wee_s[AA];
    __shared__ float convw_s[FCN * KCV];
    __shared__ float convb_s[FCN];
    __shared__ float alpha_s[132];
    __shared__ __align__(16) float WfeT[FCN * 516];
    int b = blockIdx.y;
    int t0 = blockIdx.x * 32;
    int tid = threadIdx.x;
    int len = lengths[b];
    if (t0 >= len) {
        if (tid < 32) g_e[b * TT + t0 + tid] = -1e30f;
        return;
    }
    for (int a = tid; a < AA; a += 256) {
        float v = 0.f;
#pragma unroll
        for (int p = 0; p < NSPK; p++) v += g_spart[p * BB * 3072 + b * 3072 + a];
        sE_s[a] = v;
        wee_s[a] = w_ee[a];
    }
    for (int i = tid; i < FCN * KCV; i += 256) convw_s[i] = conv_w[i];
    if (tid < FCN) convb_s[tid] = conv_b[tid];
    for (int i = tid; i < AA * FCN; i += 256) {
        int a = i >> 4, f = i & 15;
        WfeT[f * 516 + a] = W_fe[i];
    }
    if (tid < 132) {
        int tg = t0 - 50 + tid;
        alpha_s[tid] = (tg >= 0 && tg < TT) ? g_alpha[b * TT + tg] : 0.f;
    }
    __syncthreads();
    int w = tid >> 5, lane = tid & 31;
    for (int tt = w; tt < 32; tt += 8) {
        int tabs = t0 + tt;
        if (tabs >= len) {
            if (lane == 0) g_e[b * TT + tabs] = -1e30f;
            continue;
        }
        int f = lane & 15, half = lane >> 4;
        float yp = 0.f;
        int ks = half * 51, ke = half ? KCV : 51;
        for (int k = ks; k < ke; k++)
            yp = fmaf(alpha_s[tt + k], convw_s[f * KCV + k], yp);
        yp += __shfl_down_sync(0xffffffffu, yp, 16);
        if (half == 0) yp += convb_s[f];
        ull yp2[16];
#pragma unroll
        for (int ff = 0; ff < 16; ff++) yp2[ff] = pack2(__shfl_sync(0xffffffffu, yp, ff));
        const float* hEr = g_hE + ((size_t)b * TT + tabs) * AA;
        ull v2[8];
#pragma unroll
        for (int c = 0; c < 4; c++) {
            ulonglong2 h2 = *(const ulonglong2*)&hEr[c * 128 + lane * 4];
            ulonglong2 s2v = *(const ulonglong2*)&sE_s[c * 128 + lane * 4];
            v2[2 * c] = add2(h2.x, s2v.x);
            v2[2 * c + 1] = add2(h2.y, s2v.y);
        }
#pragma unroll
        for (int ff = 0; ff < 16; ff++) {
#pragma unroll
            for (int c = 0; c < 4; c++) {
                ulonglong2 w2 = *(const ulonglong2*)&WfeT[ff * 516 + c * 128 + lane * 4];
                fma2(v2[2 * c], yp2[ff], w2.x);
                fma2(v2[2 * c + 1], yp2[ff], w2.y);
            }
        }
        float acc = 0.f;
#pragma unroll
        for (int c = 0; c < 4; c++) {
            float4 we = *(const float4*)&wee_s[c * 128 + lane * 4];
            float2 a0 = unpk(v2[2 * c]);
            float2 a1 = unpk(v2[2 * c + 1]);
            acc = fmaf(tanh_fast(a0.x), we.x, acc);
            acc = fmaf(tanh_fast(a0.y), we.y, acc);
            acc = fmaf(tanh_fast(a1.x), we.z, acc);
            acc = fmaf(tanh_fast(a1.y), we.w, acc);
        }
#pragma unroll
        for (int off = 16; off; off >>= 1) acc += __shfl_down_sync(0xffffffffu, acc, off);
        if (lane == 0) g_e[b * TT + tabs] = acc;
    }
}

// ---------------- fused softmax + g = alpha @ hbatch (t-split x16) ----------------
__global__ __launch_bounds__(256) void k_gaccum(const float* __restrict__ hbatch,
                                                const int* __restrict__ lengths) {
    int b = blockIdx.x, ts = blockIdx.y;
    int tid = threadIdx.x;
    __shared__ float es[TT];
    __shared__ float red[256];
    float mx = -3e38f;
    for (int t2 = tid; t2 < TT; t2 += 256) {
        float v = g_e[b * TT + t2];
        es[t2] = v;
        mx = fmaxf(mx, v);
    }
    red[tid] = mx;
    __syncthreads();
    for (int o = 128; o; o >>= 1) {
        if (tid < o) red[tid] = fmaxf(red[tid], red[tid + o]);
        __syncthreads();
    }
    float M = red[0];
    __syncthreads();
    float sm = 0.f;
    for (int t2 = tid; t2 < TT; t2 += 256) {
        float p = __expf(es[t2] - M);
        es[t2] = p;
        sm += p;
    }
    red[tid] = sm;
    __syncthreads();
    for (int o = 128; o; o >>= 1) {
        if (tid < o) red[tid] += red[tid + o];
        __syncthreads();
    }
    float inv = 1.f / red[0];
    __syncthreads();
    for (int t2 = tid; t2 < TT; t2 += 256) es[t2] *= inv;
    __syncthreads();
    if (ts == 0)
        for (int t2 = tid; t2 < TT; t2 += 256) g_alpha[b * TT + t2] = es[t2];

    int len = lengths[b];
    int t1 = (len * ts) / NSPT, t2e = (len * (ts + 1)) / NSPT;
    int d = tid * 4;
    float4 acc = make_float4(0.f, 0.f, 0.f, 0.f);
    const float* hb = hbatch + (size_t)b * TT * DD + d;
    int t = t1;
    for (; t + 4 <= t2e; t += 4) {
        float a0 = es[t], a1 = es[t + 1], a2 = es[t + 2], a3 = es[t + 3];
        float4 h0 = *(const float4*)&hb[(size_t)t * DD];
        float4 h1 = *(const float4*)&hb[(size_t)(t + 1) * DD];
        float4 h2 = *(const float4*)&hb[(size_t)(t + 2) * DD];
        float4 h3 = *(const float4*)&hb[(size_t)(t + 3) * DD];
        acc.x = fmaf(a0, h0.x, fmaf(a1, h1.x, fmaf(a2, h2.x, fmaf(a3, h3.x, acc.x))));
        acc.y = fmaf(a0, h0.y, fmaf(a1, h1.y, fmaf(a2, h2.y, fmaf(a3, h3.y, acc.y))));
        acc.z = fmaf(a0, h0.z, fmaf(a1, h1.z, fmaf(a2, h2.z, fmaf(a3, h3.z, acc.z))));
        acc.w = fmaf(a0, h0.w, fmaf(a1, h1.w, fmaf(a2, h2.w, fmaf(a3, h3.w, acc.w))));
    }
    for (; t < t2e; t++) {
        float a0 = es[t];
        float4 h0 = *(const float4*)&hb[(size_t)t * DD];
        acc.x = fmaf(a0, h0.x, acc.x);
        acc.y = fmaf(a0, h0.y, acc.y);
        acc.z = fmaf(a0, h0.z, acc.z);
        acc.w = fmaf(a0, h0.w, acc.w);
    }
    *(float4*)&g_gp2[ts * BB * DD + b * DD + d] = acc;
}

// ---------------- LSTM cell + ypre (sums partials itself, recpre l-major) ----------------
__global__ __launch_bounds__(512) void k_cell(const float* __restrict__ b_gy, int l) {
    int b = blockIdx.x, h = threadIdx.x;
    float gy = 0.f, sy = 0.f;
#pragma unroll
    for (int p = 0; p < NSPK; p++) {
        gy += g_gpart[p * BB * 2560 + b * 2560 + h];
        sy += g_spart[p * BB * 3072 + b * 3072 + 512 + h];
    }
    float ypre = tanhf(gy + sy + b_gy[h]);
    g_ypre_all[((size_t)l * BB + b) * HH + h] = ypre;
    float r[4];
#pragma unroll
    for (int q = 0; q < 4; q++) {
        int j = q * 512 + h;
        float v = g_recpre[((size_t)l * BB + b) * 2048 + j];
#pragma unroll
        for (int p = 0; p < NSPK; p++) {
            v += g_spart[p * BB * 3072 + b * 3072 + 1024 + j];
            v += g_gpart[p * BB * 2560 + b * 2560 + 512 + j];
        }
        r[q] = v;
    }
    float c = sig_acc(r[1]) * g_c[b * HH + h] + sig_acc(r[0]) * tanhf(r[2]);
    float s = sig_acc(r[3]) * tanhf(c);
    g_c[b * HH + h] = c;
    g_s[b * HH + h] = s;
}

// ---------------- launch ----------------
extern "C" void kernel_launch(void* const* d_in, const int* in_sizes, int n_in,
                              void* d_out, int out_size) {
    const float* hbatch  = (const float*)d_in[0];
    const int*   lengths = (const int*)d_in[1];
    const float* targets = (const float*)d_in[2];
    const float* W_sy    = (const float*)d_in[3];
    const float* W_gy    = (const float*)d_in[4];
    const float* b_gy    = (const float*)d_in[5];
    const float* W_yy    = (const float*)d_in[6];
    const float* b_yy    = (const float*)d_in[7];
    const float* W_ys    = (const float*)d_in[8];
    const float* W_ss    = (const float*)d_in[9];
    const float* W_gs    = (const float*)d_in[10];
    const float* b_gs    = (const float*)d_in[11];
    const float* W_se    = (const float*)d_in[12];
    const float* W_he    = (const float*)d_in[13];
    const float* W_fe    = (const float*)d_in[14];
    const float* conv_w  = (const float*)d_in[15];
    const float* conv_b  = (const float*)d_in[16];
    const float* w_ee    = (const float*)d_in[17];
    float* out = (float*)d_out;

    static cudaStream_t s2 = nullptr;
    static cudaEvent_t evRoot, evRec[8], evY[4], evJoin;
    if (!s2) {
        cudaStreamCreateWithFlags(&s2, cudaStreamNonBlocking);
        cudaEventCreateWithFlags(&evRoot, cudaEventDisableTiming);
        for (int i = 0; i < 8; i++) cudaEventCreateWithFlags(&evRec[i], cudaEventDisableTiming);
        for (int i = 0; i < 4; i++) cudaEventCreateWithFlags(&evY[i], cudaEventDisableTiming);
        cudaEventCreateWithFlags(&evJoin, cudaEventDisableTiming);
    }

    // fork side stream from main (capturing) stream
    cudaEventRecord(evRoot, 0);
    cudaStreamWaitEvent(s2, evRoot, 0);

    // side stream: recpre = targets @ W_ys^T + b_gs, l-major rows, 8 chunks of 8 steps
    for (int c = 0; c < 8; c++) {
        int rows = (c == 7) ? 128 : 256;
        k_gemm_big<1><<<dim3(16, rows / 128), 256, 0, s2>>>(
            targets, W_ys, b_gs, nullptr, 4000, 4000, 4000, c * 256);
        cudaEventRecord(evRec[c], s2);
    }

    // main stream: init + hE
    k_init<<<2048, 256>>>(W_se, W_sy, W_ss, W_gy, W_gs);
    k_gemm_big<0><<<dim3(4, 200), 256>>>(hbatch, W_he, nullptr, nullptr, 1024, 1024, 1024, 0);

    for (int l = 0; l < LL; l++) {
        k_skinny<0><<<dim3(12, NSPK), 256>>>();
        k_attn<<<dim3(25, 32), 256>>>(lengths, W_fe, conv_w, conv_b, w_ee);
        k_gaccum<<<dim3(32, NSPT), 256>>>(hbatch, lengths);
        k_gsum<<<32, 256>>>();
        k_skinny<1><<<dim3(10, NSPK), 256>>>();
        if ((l & 7) == 0) cudaStreamWaitEvent(0, evRec[l >> 3], 0);
        k_cell<<<32, 512>>>(b_gy, l);
        // yout chunks overlap on side stream: chunk k covers l in [16k, 16k+16)
        if (l == 15 || l == 31 || l == 47 || l == 59) {
            int k = (l == 59) ? 3 : (l + 1) / 16 - 1;
            cudaEventRecord(evY[k], 0);
            cudaStreamWaitEvent(s2, evY[k], 0);
            int rows = (k == 3) ? 384 : 512;
            k_gemm_big<2><<<dim3(32, rows / 128), 256, 0, s2>>>(
                nullptr, W_yy, b_yy, out, 512, 512, 512, k * 512);
        }
    }
    // join side stream back into main
    cudaEventRecord(evJoin, s2);
    cudaStreamWaitEvent(0, evJoin, 0);
}